// round 14
// baseline (speedup 1.0000x reference)
#include <cuda_runtime.h>
#include <cstdint>

#define DINLINE __device__ __forceinline__

namespace {
constexpr int CIN = 512, PIX = 3136, NWIN = 8, WSTRIDE = 32;
constexpr int TM = 128;            // pixels per tile; 25 tiles, tile 24 half-valid
constexpr int NTILES = 25;
constexpr int NJOBS = 32 * NWIN * NTILES;  // 6400 jobs: (b, nwin, tile)
constexpr int NCTA = 296;          // 148 SMs x 2 CTAs (persistent)
constexpr int SPLIT = NJOBS - NCTA * (NJOBS / NCTA);
constexpr int JBASE = NJOBS / NCTA;
constexpr int ROWF = 136;          // padded row stride (floats) — conflict-free
constexpr int ROWB = ROWF * 4;     // 544 B
constexpr int BUFB = 64 * ROWB;    // 34816 B per buffer
constexpr int SMEM_TOTAL = 3 * BUFB;  // 104448 B (3-stage)
}

// W fragments (tf32-rounded fp32 bits), register order:
// idx = ng*2048 + ((ks*4 + j)*2 + r)*32 + lane
// n = ng*32 + j*8 + (lane>>2), k = ks*8 + (lane&3) + r*4
__device__ __align__(16) uint32_t g_wB[4096];

DINLINE uint32_t f2tf32(float f) {
    uint32_t r;
    asm("cvt.rna.tf32.f32 %0, %1;" : "=r"(r) : "f"(f));
    return r;
}

__global__ void prep_w(const float* __restrict__ w) {
    int t = threadIdx.x;
#pragma unroll
    for (int i = 0; i < 16; i++) {
        int idx  = i * 256 + t;
        int lane = idx & 31;
        int r    = (idx >> 5) & 1;
        int j    = (idx >> 6) & 3;
        int ks   = (idx >> 8) & 7;
        int ng   = (idx >> 11) & 1;
        int n = ng * 32 + j * 8 + (lane >> 2);
        int k = ks * 8 + (lane & 3) + r * 4;
        g_wB[idx] = f2tf32(w[n * 64 + k]);
    }
}

// ---- PTX helpers ----
DINLINE uint32_t smem_u32(const void* p) {
    uint32_t a;
    asm("{ .reg .u64 t; cvta.to.shared.u64 t, %1; cvt.u32.u64 %0, t; }" : "=r"(a) : "l"(p));
    return a;
}
DINLINE void cp16(uint32_t dst, const void* src) {
    asm volatile("cp.async.cg.shared.global [%0], [%1], 16;" :: "r"(dst), "l"(src) : "memory");
}
// load a pixel-pair (two fp32) and apply half-ulp-of-tf32 bias to both in one IADD64.
DINLINE void ldtf2(uint32_t& lo, uint32_t& hi, uint32_t a) {
    unsigned long long v;
    asm volatile("ld.shared.b64 %0, [%1];" : "=l"(v) : "r"(a));
    v += 0x0000100000001000ULL;
    lo = (uint32_t)v;
    hi = (uint32_t)(v >> 32);
}
DINLINE void mma_tf32(float* c, uint32_t a0, uint32_t a1, uint32_t a2, uint32_t a3,
                      uint32_t b0, uint32_t b1) {
    asm volatile(
        "mma.sync.aligned.m16n8k8.row.col.f32.tf32.tf32.f32 "
        "{%0,%1,%2,%3}, {%4,%5,%6,%7}, {%8,%9}, {%0,%1,%2,%3};"
        : "+f"(c[0]), "+f"(c[1]), "+f"(c[2]), "+f"(c[3])
        : "r"(a0), "r"(a1), "r"(a2), "r"(a3), "r"(b0), "r"(b1));
}

__global__ void __launch_bounds__(256, 2)
win_mma(const float* __restrict__ x, float* __restrict__ out) {
    extern __shared__ __align__(16) char smem[];
    const uint32_t sb = smem_u32(smem);
    const int t = threadIdx.x;
    const int lane = t & 31, w = t >> 5;
    const int mg = w & 3, ng = w >> 2;     // 4 M32-groups x 2 N32-groups

    // ---- B fragments: K=64, N=32 per warp, loaded ONCE per kernel ----
    uint32_t bw[8][4][2];
    {
        const uint32_t* base = g_wB + ng * 2048 + lane;
#pragma unroll
        for (int ks = 0; ks < 8; ks++)
#pragma unroll
            for (int j = 0; j < 4; j++)
#pragma unroll
                for (int r = 0; r < 2; r++)
                    bw[ks][j][r] = base[((ks * 4 + j) * 2 + r) * 32];
    }

    // persistent job range (contiguous chunk)
    const int c = blockIdx.x;
    const int jbeg = (c < SPLIT) ? c * (JBASE + 1) : c * JBASE + SPLIT;
    const int jend = jbeg + JBASE + (c < SPLIT ? 1 : 0);

    // staging lane pieces: 2048 x 16B chunks per tile, 8 per thread
    const int sk = t >> 5, sc = t & 31;
    // A-fragment lane pieces; row->pixel map: row r -> px 2*(r&7) + (r>>3)
    const int grp = lane >> 2, tid4 = lane & 3;
    const int kA = tid4;
    const int pxpair = mg * 32 + 2 * grp;   // + mf*16
    // per-warp ks stagger: warp w starts its k-step sweep at ks = w
    const int ks0 = w & 7;

    // stage job j into buffer bi (no-op if j >= jend); always commits a group
    auto stage = [&](int j, int bi) {
        if (j < jend) {
            int tile = j % NTILES;
            int rr = j / NTILES;
            int nwin = rr & 7, b = rr >> 3;
            const float* src = x + ((size_t)(b * CIN + nwin * WSTRIDE + sk)) * PIX +
                               tile * TM + sc * 4;
            uint32_t dst = sb + bi * BUFB + sk * ROWB + sc * 16;
#pragma unroll
            for (int i = 0; i < 8; i++)
                cp16(dst + i * 8 * ROWB, src + (size_t)(i * 8) * PIX);
        }
        asm volatile("cp.async.commit_group;" ::: "memory");
    };

    // ---- prologue: depth-2 prefetch ----
    stage(jbeg, 0);
    stage(jbeg + 1, 1);

    for (int i = jbeg; i < jend; i++) {
        asm volatile("cp.async.wait_group 1;" ::: "memory");
        __syncthreads();   // job i's data visible; prior iter's reads done

        // stage job i+2 NOW: its buffer's readers all passed the sync above
        stage(i + 2, (i - jbeg + 2) % 3);

        const int tile = i % NTILES;
        const int rr = i / NTILES;
        const int nwin = rr & 7, b = rr >> 3;

        // ---- MMA: warp tile M32 x N32, segment-pipelined A, warp-staggered ks ----
        float acc[2][4][4];
#pragma unroll
        for (int mf = 0; mf < 2; mf++)
#pragma unroll
            for (int j = 0; j < 4; j++)
#pragma unroll
                for (int q = 0; q < 4; q++) acc[mf][j][q] = 0.0f;

        const uint32_t bufb = sb + ((i - jbeg) % 3) * BUFB;
        auto aaddr = [&](int ks, int mf) {
            return bufb + (uint32_t)((ks * 8 + kA) * ROWB + (pxpair + mf * 16) * 4);
        };

        uint32_t A[2][4];   // double-buffered A fragments
        {
            uint32_t ad = aaddr(ks0, 0);
            ldtf2(A[0][0], A[0][1], ad);
            ldtf2(A[0][2], A[0][3], ad + 4 * ROWB);
        }
#pragma unroll
        for (int s = 0; s < 16; s++) {
            const int mf = s & 1;
            const int ks = ((s >> 1) + ks0) & 7;   // physical k-step (staggered)
            if (s < 15) {                          // prefetch next segment
                const int s1 = s + 1;
                const int ks1 = ((s1 >> 1) + ks0) & 7;
                uint32_t ad = aaddr(ks1, s1 & 1);
                ldtf2(A[s1 & 1][0], A[s1 & 1][1], ad);
                ldtf2(A[s1 & 1][2], A[s1 & 1][3], ad + 4 * ROWB);
            }
            const uint32_t* a = A[s & 1];
#pragma unroll
            for (int j = 0; j < 4; j++)
                mma_tf32(acc[mf][j], a[0], a[1], a[2], a[3], bw[ks][j][0], bw[ks][j][1]);
        }

        // ---- epilogue: paired STG.64 per (o, pixel-pair); guarded for tail ----
        float* ob = out + ((size_t)(b * CIN + nwin)) * PIX;
#pragma unroll
        for (int mf = 0; mf < 2; mf++) {
            const int px0 = tile * TM + pxpair + mf * 16;   // even; pair = px0, px0+1
            if (px0 + 1 < PIX) {
#pragma unroll
                for (int j = 0; j < 4; j++) {
                    int o = ng * 32 + j * 8 + tid4 * 2;
                    size_t s0 = (size_t)(o * NWIN) * PIX;
                    size_t s1 = s0 + (size_t)NWIN * PIX;
                    *(float2*)(ob + s0 + px0) = make_float2(acc[mf][j][0], acc[mf][j][2]);
                    *(float2*)(ob + s1 + px0) = make_float2(acc[mf][j][1], acc[mf][j][3]);
                }
            }
        }
    }
}

extern "C" void kernel_launch(void* const* d_in, const int* in_sizes, int n_in,
                              void* d_out, int out_size) {
    const float* x = (const float*)d_in[0];   // (32, 512, 56, 56) fp32
    const float* w = (const float*)d_in[1];   // (64, 64) fp32
    float* out = (float*)d_out;               // (32, 512, 56, 56) fp32

    cudaFuncSetAttribute(win_mma, cudaFuncAttributeMaxDynamicSharedMemorySize, SMEM_TOTAL);
    prep_w<<<1, 256>>>(w);
    win_mma<<<NCTA, 256, SMEM_TOTAL>>>(x, out);
}

// round 15
// speedup vs baseline: 1.5249x; 1.5249x over previous
#include <cuda_runtime.h>
#include <cstdint>

#define DINLINE __device__ __forceinline__

namespace {
constexpr int CIN = 512, PIX = 3136, NWIN = 8, WSTRIDE = 32;
constexpr int TM = 128;            // pixels per tile; 25 tiles, tile 24 half-valid
constexpr int NTILES = 25;
constexpr int NJOBS = 32 * NWIN * NTILES;  // 6400 jobs: (b, nwin, tile)
constexpr int NCTA = 296;          // 148 SMs x 2 CTAs (persistent)
constexpr int SPLIT = NJOBS - NCTA * (NJOBS / NCTA);
constexpr int JBASE = NJOBS / NCTA;
constexpr int ROWF = 136;          // padded row stride (floats) — conflict-free
constexpr int ROWB = ROWF * 4;     // 544 B
constexpr int BUFB = 64 * ROWB;    // 34816 B per buffer
constexpr int SMEM_TOTAL = 3 * BUFB;  // 104448 B (3-stage)
}

// W fragments (tf32-rounded fp32 bits), register order:
// idx = ng*2048 + ((ks*4 + j)*2 + r)*32 + lane
// n = ng*32 + j*8 + (lane>>2), k = ks*8 + (lane&3) + r*4
__device__ __align__(16) uint32_t g_wB[4096];

DINLINE uint32_t f2tf32(float f) {
    uint32_t r;
    asm("cvt.rna.tf32.f32 %0, %1;" : "=r"(r) : "f"(f));
    return r;
}

__global__ void prep_w(const float* __restrict__ w) {
    int t = threadIdx.x;
#pragma unroll
    for (int i = 0; i < 16; i++) {
        int idx  = i * 256 + t;
        int lane = idx & 31;
        int r    = (idx >> 5) & 1;
        int j    = (idx >> 6) & 3;
        int ks   = (idx >> 8) & 7;
        int ng   = (idx >> 11) & 1;
        int n = ng * 32 + j * 8 + (lane >> 2);
        int k = ks * 8 + (lane & 3) + r * 4;
        g_wB[idx] = f2tf32(w[n * 64 + k]);
    }
}

// ---- PTX helpers ----
DINLINE uint32_t smem_u32(const void* p) {
    uint32_t a;
    asm("{ .reg .u64 t; cvta.to.shared.u64 t, %1; cvt.u32.u64 %0, t; }" : "=r"(a) : "l"(p));
    return a;
}
DINLINE void cp16(uint32_t dst, const void* src) {
    asm volatile("cp.async.cg.shared.global [%0], [%1], 16;" :: "r"(dst), "l"(src) : "memory");
}
// load a pixel-pair (two fp32) and apply half-ulp-of-tf32 bias to both in one IADD64.
DINLINE void ldtf2(uint32_t& lo, uint32_t& hi, uint32_t a) {
    unsigned long long v;
    asm volatile("ld.shared.b64 %0, [%1];" : "=l"(v) : "r"(a));
    v += 0x0000100000001000ULL;
    lo = (uint32_t)v;
    hi = (uint32_t)(v >> 32);
}
DINLINE void mma_tf32(float* c, uint32_t a0, uint32_t a1, uint32_t a2, uint32_t a3,
                      uint32_t b0, uint32_t b1) {
    asm volatile(
        "mma.sync.aligned.m16n8k8.row.col.f32.tf32.tf32.f32 "
        "{%0,%1,%2,%3}, {%4,%5,%6,%7}, {%8,%9}, {%0,%1,%2,%3};"
        : "+f"(c[0]), "+f"(c[1]), "+f"(c[2]), "+f"(c[3])
        : "r"(a0), "r"(a1), "r"(a2), "r"(a3), "r"(b0), "r"(b1));
}

__global__ void __launch_bounds__(256, 2)
win_mma(const float* __restrict__ x, float* __restrict__ out) {
    extern __shared__ __align__(16) char smem[];
    const uint32_t sb = smem_u32(smem);
    const int t = threadIdx.x;
    const int lane = t & 31, w = t >> 5;
    const int mg = w & 3, ng = w >> 2;     // 4 M32-groups x 2 N32-groups

    // ---- B fragments: K=64, N=32 per warp, loaded ONCE per kernel ----
    uint32_t bw[8][4][2];
    {
        const uint32_t* base = g_wB + ng * 2048 + lane;
#pragma unroll
        for (int ks = 0; ks < 8; ks++)
#pragma unroll
            for (int j = 0; j < 4; j++)
#pragma unroll
                for (int r = 0; r < 2; r++)
                    bw[ks][j][r] = base[((ks * 4 + j) * 2 + r) * 32];
    }

    // persistent job range (contiguous chunk)
    const int c = blockIdx.x;
    const int jbeg = (c < SPLIT) ? c * (JBASE + 1) : c * JBASE + SPLIT;
    const int jend = jbeg + JBASE + (c < SPLIT ? 1 : 0);

    // staging lane pieces: 2048 x 16B chunks per tile, 8 per thread
    const int sk = t >> 5, sc = t & 31;
    // A-fragment lane pieces; row->pixel map: row r -> px 2*(r&7) + (r>>3)
    const int grp = lane >> 2, tid4 = lane & 3;
    const int kA = tid4;
    const int pxpair = mg * 32 + 2 * grp;   // + mf*16

    // stage job j into buffer bi (no-op if j >= jend); always commits a group
    auto stage = [&](int j, int bi) {
        if (j < jend) {
            int tile = j % NTILES;
            int rr = j / NTILES;
            int nwin = rr & 7, b = rr >> 3;
            const float* src = x + ((size_t)(b * CIN + nwin * WSTRIDE + sk)) * PIX +
                               tile * TM + sc * 4;
            uint32_t dst = sb + bi * BUFB + sk * ROWB + sc * 16;
#pragma unroll
            for (int i = 0; i < 8; i++)
                cp16(dst + i * 8 * ROWB, src + (size_t)(i * 8) * PIX);
        }
        asm volatile("cp.async.commit_group;" ::: "memory");
    };

    // ---- prologue: depth-2 prefetch ----
    stage(jbeg, 0);
    stage(jbeg + 1, 1);

    for (int i = jbeg; i < jend; i++) {
        asm volatile("cp.async.wait_group 1;" ::: "memory");
        __syncthreads();   // job i's data visible; prior iter's reads done

        // stage job i+2 NOW: its buffer's readers all passed the sync above
        stage(i + 2, (i - jbeg + 2) % 3);

        const int tile = i % NTILES;
        const int rr = i / NTILES;
        const int nwin = rr & 7, b = rr >> 3;

        // ---- MMA: warp tile M32 x N32, segment-pipelined A (compile-time ks) ----
        float acc[2][4][4];
#pragma unroll
        for (int mf = 0; mf < 2; mf++)
#pragma unroll
            for (int j = 0; j < 4; j++)
#pragma unroll
                for (int q = 0; q < 4; q++) acc[mf][j][q] = 0.0f;

        const uint32_t bufb = sb + ((i - jbeg) % 3) * BUFB;
        auto aaddr = [&](int ks, int mf) {
            return bufb + (uint32_t)((ks * 8 + kA) * ROWB + (pxpair + mf * 16) * 4);
        };

        uint32_t A[2][4];   // double-buffered A fragments
        {
            uint32_t ad = aaddr(0, 0);
            ldtf2(A[0][0], A[0][1], ad);
            ldtf2(A[0][2], A[0][3], ad + 4 * ROWB);
        }
#pragma unroll
        for (int s = 0; s < 16; s++) {       // segment: ks = s>>1 (compile-time), mf = s&1
            const int mf = s & 1;
            const int ks = s >> 1;
            if (s < 15) {                    // prefetch next segment's A
                const int s1 = s + 1;
                uint32_t ad = aaddr(s1 >> 1, s1 & 1);
                ldtf2(A[s1 & 1][0], A[s1 & 1][1], ad);
                ldtf2(A[s1 & 1][2], A[s1 & 1][3], ad + 4 * ROWB);
            }
            const uint32_t* a = A[s & 1];
#pragma unroll
            for (int j = 0; j < 4; j++)
                mma_tf32(acc[mf][j], a[0], a[1], a[2], a[3], bw[ks][j][0], bw[ks][j][1]);
        }

        // ---- epilogue: paired STG.64 per (o, pixel-pair); guarded for tail ----
        float* ob = out + ((size_t)(b * CIN + nwin)) * PIX;
#pragma unroll
        for (int mf = 0; mf < 2; mf++) {
            const int px0 = tile * TM + pxpair + mf * 16;   // even; pair = px0, px0+1
            if (px0 + 1 < PIX) {
#pragma unroll
                for (int j = 0; j < 4; j++) {
                    int o = ng * 32 + j * 8 + tid4 * 2;
                    size_t s0 = (size_t)(o * NWIN) * PIX;
                    size_t s1 = s0 + (size_t)NWIN * PIX;
                    *(float2*)(ob + s0 + px0) = make_float2(acc[mf][j][0], acc[mf][j][2]);
                    *(float2*)(ob + s1 + px0) = make_float2(acc[mf][j][1], acc[mf][j][3]);
                }
            }
        }
    }
}

extern "C" void kernel_launch(void* const* d_in, const int* in_sizes, int n_in,
                              void* d_out, int out_size) {
    const float* x = (const float*)d_in[0];   // (32, 512, 56, 56) fp32
    const float* w = (const float*)d_in[1];   // (64, 64) fp32
    float* out = (float*)d_out;               // (32, 512, 56, 56) fp32

    cudaFuncSetAttribute(win_mma, cudaFuncAttributeMaxDynamicSharedMemorySize, SMEM_TOTAL);
    prep_w<<<1, 256>>>(w);
    win_mma<<<NCTA, 256, SMEM_TOTAL>>>(x, out);
}